// round 13
// baseline (speedup 1.0000x reference)
#include <cuda_runtime.h>
#include <cuda_fp16.h>
#include <math.h>
#include <stdint.h>

#define N_ROWS_MAX 100000
#define D 64
#define NGH 16
#define NSC 10
#define EPSF 1e-10f
#define FULL 0xFFFFFFFFu

#define WPB 8           // warps per block
#define RPW 16          // rows per warp
#define RPB 128         // rows per block

#define ASTRIDE 136     // A-tile row stride in halfs (272B) — conflict-free

typedef unsigned long long ull;

// ---- scratch (device globals per allocation rules) ----
// g_fused[row*16+sub] = { rs_hat01, rs_hat23, ce01, ce23 } all fp16x2
__device__ uint4   g_fused[(size_t)N_ROWS_MAX * 16];
__device__ float2  g_ss[N_ROWS_MAX];                 // (scale = sq+eps, selfsim)
__device__ uint2   g_Bfrag[64 * 32];                 // [kstep*8+ntile][lane]

// ---- packed f32x2 helpers ----
__device__ __forceinline__ ull pk2(float x, float y) {
    ull r; asm("mov.b64 %0, {%1, %2};" : "=l"(r) : "f"(x), "f"(y)); return r;
}
__device__ __forceinline__ float2 upk2(ull v) {
    float2 r; asm("mov.b64 {%0, %1}, %2;" : "=f"(r.x), "=f"(r.y) : "l"(v)); return r;
}
__device__ __forceinline__ void fma2(ull& d, ull a, ull b, ull c) {
    asm("fma.rn.f32x2 %0, %1, %2, %3;" : "=l"(d) : "l"(a), "l"(b), "l"(c));
}
__device__ __forceinline__ float2 h2f(unsigned int h) {
    return __half22float2(*reinterpret_cast<__half2*>(&h));
}

// ---------------------------------------------------------------------------
// Kernel A: per-row scene sums -> fused fp16 table {rs_hat, ce} +
// (scale, selfsim); also builds per-lane HMMA B fragments of agg_W.
// ---------------------------------------------------------------------------
__global__ void rowsum_kernel(const float* __restrict__ scene_emb,
                              const int* __restrict__ cate_scene_pad,
                              const float* __restrict__ agg_W,
                              const float* __restrict__ cate_emb,
                              int n_rows) {
    int gtid = blockIdx.x * blockDim.x + threadIdx.x;

    // B-fragment build: first 2048 threads, one uint2 each.
    if (gtid < 64 * 32) {
        int lane  = gtid & 31;
        int tile  = gtid >> 5;
        int kstep = tile >> 3;
        int ntile = tile & 7;
        int tid4  = lane & 3;
        int gid   = lane >> 2;
        int k0 = kstep * 16 + tid4 * 2;
        int n  = ntile * 8 + gid;
        __half2 r0 = __floats2half2_rn(agg_W[n * 128 + k0],     agg_W[n * 128 + k0 + 1]);
        __half2 r1 = __floats2half2_rn(agg_W[n * 128 + k0 + 8], agg_W[n * 128 + k0 + 9]);
        uint2 u;
        u.x = *reinterpret_cast<unsigned int*>(&r0);
        u.y = *reinterpret_cast<unsigned int*>(&r1);
        g_Bfrag[tile * 32 + lane] = u;
    }

    int row = gtid >> 4;
    int sub = gtid & 15;
    if (row >= n_rows) return;
    int lane = threadIdx.x & 31;
    int group_base = lane & 16;

    int myidx = 0;
    if (sub < NSC) myidx = __ldg(cate_scene_pad + (size_t)row * NSC + sub);

    // independent ce load for the fused table (overlaps scene gathers)
    float4 ce = __ldg((const float4*)(cate_emb + (size_t)row * D) + sub);

    float4 acc = make_float4(0.f, 0.f, 0.f, 0.f);
#pragma unroll
    for (int k = 0; k < NSC; k++) {
        int j = __shfl_sync(FULL, myidx, group_base + k);
        float4 v = ((const float4*)(scene_emb + (size_t)j * D))[sub];
        acc.x += v.x; acc.y += v.y; acc.z += v.z; acc.w += v.w;
    }

    float sq = acc.x * acc.x + acc.y * acc.y + acc.z * acc.z + acc.w * acc.w;
#pragma unroll
    for (int o = 8; o >= 1; o >>= 1)
        sq += __shfl_xor_sync(FULL, sq, o);

    float scale = sq + EPSF;
    float inv = 1.0f / scale;

    __half2 h0 = __floats2half2_rn(acc.x * inv, acc.y * inv);
    __half2 h1 = __floats2half2_rn(acc.z * inv, acc.w * inv);
    __half2 c0 = __floats2half2_rn(ce.x, ce.y);
    __half2 c1 = __floats2half2_rn(ce.z, ce.w);
    uint4 w;
    w.x = *reinterpret_cast<unsigned int*>(&h0);
    w.y = *reinterpret_cast<unsigned int*>(&h1);
    w.z = *reinterpret_cast<unsigned int*>(&c0);
    w.w = *reinterpret_cast<unsigned int*>(&c1);
    g_fused[(size_t)row * 16 + sub] = w;

    if (sub == 0) g_ss[row] = make_float2(scale, sq * inv * inv);
}

// Butterfly merge at xor-offset o.
__device__ __forceinline__ float bmerge(float a, float b, int o, int lane) {
    float x = (lane & o) ? b : a;
    float y = (lane & o) ? a : b;
    y = __shfl_xor_sync(FULL, y, o);
    return x + y;
}

__device__ __forceinline__ void mma16816(float* c, uint32_t a0, uint32_t a1,
                                         uint32_t a2, uint32_t a3,
                                         uint32_t b0, uint32_t b1) {
    asm volatile(
        "mma.sync.aligned.m16n8k16.row.col.f32.f16.f16.f32 "
        "{%0,%1,%2,%3}, {%4,%5,%6,%7}, {%8,%9}, {%0,%1,%2,%3};"
        : "+f"(c[0]), "+f"(c[1]), "+f"(c[2]), "+f"(c[3])
        : "r"(a0), "r"(a1), "r"(a2), "r"(a3), "r"(b0), "r"(b1));
}

// ---------------------------------------------------------------------------
// Kernel B: each warp owns 16 rows end-to-end.
//   Phase 1: half-warp row-pair attention. Dot gathers read the first 8B of
//            each fused 16B entry (L2); agg re-reads the second 8B of the
//            SAME line (L1 hit) — no second L2 wave.
//   Phase 2: 64x HMMA m16n8k16; bias+ELU; direct STG.
// ---------------------------------------------------------------------------
__global__ void __launch_bounds__(256, 4)
main_kernel(const int* __restrict__ c_cate_pad,
            const float* __restrict__ agg_b,
            float* __restrict__ out,
            int n_rows, int v_cates) {
    __shared__ __half sA[RPB * ASTRIDE];   // 128 rows x 136 halfs (pad 8)

    int tid  = threadIdx.x;
    int warp = tid >> 5;
    int lane = tid & 31;

    int rowbase = blockIdx.x * RPB + warp * RPW;
    int half = lane >> 4;
    int sub  = lane & 15;
    int base = lane & 16;

    // ---- batched neighbor-index prefetch for all 8 row-pair iterations ----
    int nid[RPW / 2];
#pragma unroll
    for (int rp = 0; rp < RPW / 2; rp++) {
        int row  = rowbase + 2 * rp + half;
        int vrow = row < n_rows ? row : n_rows - 1;
        nid[rp] = __ldg(c_cate_pad + (size_t)vrow * NGH + sub);
    }

    // ---- Phase 1: attention, 2 rows per iteration ----
#pragma unroll 1
    for (int rp = 0; rp < RPW / 2; rp++) {
        int row  = rowbase + 2 * rp + half;
        int vrow = row < n_rows ? row : n_rows - 1;
        int nidx = nid[rp];

        uint4 uf = __ldg(&g_fused[(size_t)vrow * 16 + sub]);
        float2 sf0 = h2f(uf.x);
        float2 sf1 = h2f(uf.y);
        float2 ss = g_ss[vrow];                 // (scale, selfsim)

        // 16 neighbor dot partials (first 8B of fused entries, L2)
        float dtp[16];
#pragma unroll
        for (int j = 0; j < 16; j++) {
            int p = __shfl_sync(FULL, nidx, base + j);
            uint2 u = __ldg((const uint2*)&g_fused[(size_t)p * 16 + sub]);
            float2 f0 = h2f(u.x);
            float2 f1 = h2f(u.y);
            dtp[j] = fmaf(f0.x, sf0.x, fmaf(f0.y, sf0.y,
                      fmaf(f1.x, sf1.x, f1.y * sf1.y)));
        }

#pragma unroll
        for (int i = 0; i < 8; i++) dtp[i] = bmerge(dtp[i], dtp[i + 8], 8, lane);
#pragma unroll
        for (int i = 0; i < 4; i++) dtp[i] = bmerge(dtp[i], dtp[i + 4], 4, lane);
#pragma unroll
        for (int i = 0; i < 2; i++) dtp[i] = bmerge(dtp[i], dtp[i + 2], 2, lane);
        dtp[0] = bmerge(dtp[0], dtp[1], 1, lane);

        float miu = (nidx < v_cates - 1) ? __expf(dtp[0]) : 0.f;

        float dv = miu;
#pragma unroll
        for (int o = 8; o >= 1; o >>= 1)
            dv += __shfl_xor_sync(FULL, dv, o);

        float miu_self = (vrow < v_cates - 1) ? __expf(ss.y) : 0.f;
        float rden = 1.0f / (dv + miu_self + EPSF);

        // aggregation: second 8B of the same fused lines (L1-resident)
        float2 cs0 = h2f(uf.z);
        float2 cs1 = h2f(uf.w);
        ull msd = pk2(miu_self, miu_self);
        ull acc01, acc23;
        fma2(acc01, msd, pk2(cs0.x, cs0.y), pk2(0.f, 0.f));
        fma2(acc23, msd, pk2(cs1.x, cs1.y), pk2(0.f, 0.f));
#pragma unroll
        for (int j = 0; j < 16; j++) {
            float m = __shfl_sync(FULL, miu, base + j);
            int   p = __shfl_sync(FULL, nidx, base + j);
            uint2 c = __ldg(((const uint2*)&g_fused[(size_t)p * 16 + sub]) + 1);
            float2 f0 = h2f(c.x);
            float2 f1 = h2f(c.y);
            ull mm = pk2(m, m);
            fma2(acc01, mm, pk2(f0.x, f0.y), acc01);
            fma2(acc23, mm, pk2(f1.x, f1.y), acc23);
        }
        float2 g01 = upk2(acc01);
        float2 g23 = upk2(acc23);

        // h store (fp16): rs part at e=4sub..4sub+3, agg at e=64+4sub..
        int rt = warp * RPW + 2 * rp + half;
        __half* hrow = sA + rt * ASTRIDE;
        float sc = ss.x;
        __half2 p0 = __floats2half2_rn(sf0.x * sc, sf0.y * sc);
        __half2 p1 = __floats2half2_rn(sf1.x * sc, sf1.y * sc);
        uint2 w0;
        w0.x = *reinterpret_cast<unsigned int*>(&p0);
        w0.y = *reinterpret_cast<unsigned int*>(&p1);
        *(uint2*)(hrow + 4 * sub) = w0;

        __half2 q0 = __floats2half2_rn(g01.x * rden, g01.y * rden);
        __half2 q1 = __floats2half2_rn(g23.x * rden, g23.y * rden);
        uint2 w1;
        w1.x = *reinterpret_cast<unsigned int*>(&q0);
        w1.y = *reinterpret_cast<unsigned int*>(&q1);
        *(uint2*)(hrow + 64 + 4 * sub) = w1;
    }
    __syncwarp();

    // ---- Phase 2: HMMA matvec, 16 rows x 64 cols per warp ----
    int gid  = lane >> 2;      // 0..7
    int tid4 = lane & 3;       // 0..3

    float acc[8][4];
#pragma unroll
    for (int n = 0; n < 8; n++)
#pragma unroll
        for (int i = 0; i < 4; i++) acc[n][i] = 0.f;

    const __half* a_base0 = sA + (warp * RPW + gid) * ASTRIDE + tid4 * 2;
    const __half* a_base1 = a_base0 + 8 * ASTRIDE;

#pragma unroll
    for (int k = 0; k < 8; k++) {
        uint32_t a0 = *(const uint32_t*)(a_base0 + k * 16);
        uint32_t a1 = *(const uint32_t*)(a_base1 + k * 16);
        uint32_t a2 = *(const uint32_t*)(a_base0 + k * 16 + 8);
        uint32_t a3 = *(const uint32_t*)(a_base1 + k * 16 + 8);
#pragma unroll
        for (int n = 0; n < 8; n++) {
            uint2 bf = __ldg(&g_Bfrag[(k * 8 + n) * 32 + lane]);
            mma16816(acc[n], a0, a1, a2, a3, bf.x, bf.y);
        }
    }

    // ---- epilogue: bias + ELU + direct stores ----
    int grow0 = rowbase + gid;
    int grow1 = grow0 + 8;
#pragma unroll
    for (int n = 0; n < 8; n++) {
        int col = n * 8 + tid4 * 2;
        float2 bb = *(const float2*)(agg_b + col);
        if (grow0 < n_rows) {
            float v0 = acc[n][0] + bb.x;
            float v1 = acc[n][1] + bb.y;
            v0 = v0 > 0.f ? v0 : (__expf(v0) - 1.f);
            v1 = v1 > 0.f ? v1 : (__expf(v1) - 1.f);
            *(float2*)(out + (size_t)grow0 * D + col) = make_float2(v0, v1);
        }
        if (grow1 < n_rows) {
            float v2 = acc[n][2] + bb.x;
            float v3 = acc[n][3] + bb.y;
            v2 = v2 > 0.f ? v2 : (__expf(v2) - 1.f);
            v3 = v3 > 0.f ? v3 : (__expf(v3) - 1.f);
            *(float2*)(out + (size_t)grow1 * D + col) = make_float2(v2, v3);
        }
    }
}

// ---------------------------------------------------------------------------
// Inputs (metadata order):
//  0 cids, 1 cate_emb_w [Vc,64], 2 scene_emb_w [Vs,64], 3 cate_scene_pad [N,10],
//  4 c_cate_pad [N,16], 5 agg_W [64,128], 6 agg_b [64]   -> out f32 [N,64]
// ---------------------------------------------------------------------------
extern "C" void kernel_launch(void* const* d_in, const int* in_sizes, int n_in,
                              void* d_out, int out_size) {
    const float* cate_emb       = (const float*)d_in[1];
    const float* scene_emb      = (const float*)d_in[2];
    const int*   cate_scene_pad = (const int*)d_in[3];
    const int*   c_cate_pad     = (const int*)d_in[4];
    const float* agg_W          = (const float*)d_in[5];
    const float* agg_b          = (const float*)d_in[6];
    float* out = (float*)d_out;

    int n_rows  = in_sizes[4] / NGH;   // 100000
    int v_cates = in_sizes[1] / D;     // 100000

    int threadsA = 256;
    int blocksA = (n_rows * 16 + threadsA - 1) / threadsA;
    rowsum_kernel<<<blocksA, threadsA>>>(scene_emb, cate_scene_pad, agg_W,
                                         cate_emb, n_rows);

    int blocksB = (n_rows + RPB - 1) / RPB;
    main_kernel<<<blocksB, 256>>>(c_cate_pad, agg_b, out, n_rows, v_cates);
}

// round 14
// speedup vs baseline: 1.0281x; 1.0281x over previous
#include <cuda_runtime.h>
#include <cuda_fp16.h>
#include <math.h>
#include <stdint.h>

#define N_ROWS_MAX 100000
#define D 64
#define NGH 16
#define NSC 10
#define EPSF 1e-10f
#define FULL 0xFFFFFFFFu

#define WPB 8           // warps per block
#define RPW 16          // rows per warp
#define RPB 128         // rows per block

#define ASTRIDE 136     // A-tile row stride in halfs (272B) — conflict-free

typedef unsigned long long ull;

// ---- scratch (device globals per allocation rules) ----
__device__ __half2 g_rs_h[(size_t)N_ROWS_MAX * 32];  // rs/(||rs||^2+eps) fp16
__device__ float2  g_ss[N_ROWS_MAX];                 // (scale = sq+eps, selfsim)
__device__ uint2   g_Bfrag[64 * 32];                 // [kstep*8+ntile][lane]

// ---- packed f32x2 helpers ----
__device__ __forceinline__ ull pk2(float x, float y) {
    ull r; asm("mov.b64 %0, {%1, %2};" : "=l"(r) : "f"(x), "f"(y)); return r;
}
__device__ __forceinline__ float2 upk2(ull v) {
    float2 r; asm("mov.b64 {%0, %1}, %2;" : "=f"(r.x), "=f"(r.y) : "l"(v)); return r;
}
__device__ __forceinline__ void fma2(ull& d, ull a, ull b, ull c) {
    asm("fma.rn.f32x2 %0, %1, %2, %3;" : "=l"(d) : "l"(a), "l"(b), "l"(c));
}
__device__ __forceinline__ void add2(ull& d, ull a, ull b) {
    asm("add.rn.f32x2 %0, %1, %2;" : "=l"(d) : "l"(a), "l"(b));
}

// ---------------------------------------------------------------------------
// Kernel A: per-row scene sums -> fp16 normalized table + (scale, selfsim);
// also builds per-lane HMMA B fragments of agg_W.
// ---------------------------------------------------------------------------
__global__ void rowsum_kernel(const float* __restrict__ scene_emb,
                              const int* __restrict__ cate_scene_pad,
                              const float* __restrict__ agg_W,
                              int n_rows) {
    int gtid = blockIdx.x * blockDim.x + threadIdx.x;

    // B-fragment build: first 2048 threads, one uint2 each.
    if (gtid < 64 * 32) {
        int lane  = gtid & 31;
        int tile  = gtid >> 5;
        int kstep = tile >> 3;
        int ntile = tile & 7;
        int tid4  = lane & 3;
        int gid   = lane >> 2;
        int k0 = kstep * 16 + tid4 * 2;
        int n  = ntile * 8 + gid;
        __half2 r0 = __floats2half2_rn(agg_W[n * 128 + k0],     agg_W[n * 128 + k0 + 1]);
        __half2 r1 = __floats2half2_rn(agg_W[n * 128 + k0 + 8], agg_W[n * 128 + k0 + 9]);
        uint2 u;
        u.x = *reinterpret_cast<unsigned int*>(&r0);
        u.y = *reinterpret_cast<unsigned int*>(&r1);
        g_Bfrag[tile * 32 + lane] = u;
    }

    int row = gtid >> 4;
    int sub = gtid & 15;
    if (row >= n_rows) return;
    int lane = threadIdx.x & 31;
    int group_base = lane & 16;

    int myidx = 0;
    if (sub < NSC) myidx = __ldg(cate_scene_pad + (size_t)row * NSC + sub);

    float4 acc = make_float4(0.f, 0.f, 0.f, 0.f);
#pragma unroll
    for (int k = 0; k < NSC; k++) {
        int j = __shfl_sync(FULL, myidx, group_base + k);
        float4 v = ((const float4*)(scene_emb + (size_t)j * D))[sub];
        acc.x += v.x; acc.y += v.y; acc.z += v.z; acc.w += v.w;
    }

    float sq = acc.x * acc.x + acc.y * acc.y + acc.z * acc.z + acc.w * acc.w;
#pragma unroll
    for (int o = 8; o >= 1; o >>= 1)
        sq += __shfl_xor_sync(FULL, sq, o);

    float scale = sq + EPSF;
    float inv = 1.0f / scale;

    __half2 h0 = __floats2half2_rn(acc.x * inv, acc.y * inv);
    __half2 h1 = __floats2half2_rn(acc.z * inv, acc.w * inv);
    uint2 u;
    u.x = *reinterpret_cast<unsigned int*>(&h0);
    u.y = *reinterpret_cast<unsigned int*>(&h1);
    ((uint2*)g_rs_h)[(size_t)row * 16 + sub] = u;

    if (sub == 0) g_ss[row] = make_float2(scale, sq * inv * inv);
}

// Butterfly merge at xor-offset o.
__device__ __forceinline__ float bmerge(float a, float b, int o, int lane) {
    float x = (lane & o) ? b : a;
    float y = (lane & o) ? a : b;
    y = __shfl_xor_sync(FULL, y, o);
    return x + y;
}

__device__ __forceinline__ void mma16816(float* c, uint32_t a0, uint32_t a1,
                                         uint32_t a2, uint32_t a3,
                                         uint32_t b0, uint32_t b1) {
    asm volatile(
        "mma.sync.aligned.m16n8k16.row.col.f32.f16.f16.f32 "
        "{%0,%1,%2,%3}, {%4,%5,%6,%7}, {%8,%9}, {%0,%1,%2,%3};"
        : "+f"(c[0]), "+f"(c[1]), "+f"(c[2]), "+f"(c[3])
        : "r"(a0), "r"(a1), "r"(a2), "r"(a3), "r"(b0), "r"(b1));
}

// ---------------------------------------------------------------------------
// Kernel B: each warp owns 16 rows end-to-end.
//   Phase 1: half-warp row-pair attention. nidx batched; self data prefetched
//            one iteration ahead; agg accumulated on split even/odd chains.
//   Phase 2: 64x HMMA m16n8k16 -> out[16][64] per warp; bias+ELU; direct STG.
// ---------------------------------------------------------------------------
__global__ void __launch_bounds__(256, 4)
main_kernel(const float* __restrict__ cate_emb,
            const int* __restrict__ c_cate_pad,
            const float* __restrict__ agg_b,
            float* __restrict__ out,
            int n_rows, int v_cates) {
    __shared__ __half sA[RPB * ASTRIDE];   // 128 rows x 136 halfs (pad 8)

    int tid  = threadIdx.x;
    int warp = tid >> 5;
    int lane = tid & 31;

    int rowbase = blockIdx.x * RPB + warp * RPW;
    int half = lane >> 4;
    int sub  = lane & 15;
    int base = lane & 16;

    // ---- batched neighbor-index prefetch for all 8 row-pair iterations ----
    int nid[RPW / 2];
#pragma unroll
    for (int rp = 0; rp < RPW / 2; rp++) {
        int row  = rowbase + 2 * rp + half;
        int vrow = row < n_rows ? row : n_rows - 1;
        nid[rp] = __ldg(c_cate_pad + (size_t)vrow * NGH + sub);
    }

    // ---- self-data prefetch for iteration 0 ----
    int vrow0;
    {
        int row0 = rowbase + half;
        vrow0 = row0 < n_rows ? row0 : n_rows - 1;
    }
    uint2  usn = __ldg((const uint2*)g_rs_h + (size_t)vrow0 * 16 + sub);
    float2 ssn = g_ss[vrow0];

    // ---- Phase 1: attention, 2 rows per iteration ----
#pragma unroll 1
    for (int rp = 0; rp < RPW / 2; rp++) {
        int vrow = vrow0;
        uint2  us = usn;
        float2 ss = ssn;
        int nidx = nid[rp];

        // prefetch next iteration's self data
        if (rp + 1 < RPW / 2) {
            int rown = rowbase + 2 * (rp + 1) + half;
            vrow0 = rown < n_rows ? rown : n_rows - 1;
            usn = __ldg((const uint2*)g_rs_h + (size_t)vrow0 * 16 + sub);
            ssn = g_ss[vrow0];
        }

        float2 sf0 = __half22float2(*reinterpret_cast<__half2*>(&us.x));
        float2 sf1 = __half22float2(*reinterpret_cast<__half2*>(&us.y));

        float dtp[16];
#pragma unroll
        for (int j = 0; j < 16; j++) {
            int p = __shfl_sync(FULL, nidx, base + j);
            uint2 u = __ldg((const uint2*)g_rs_h + (size_t)p * 16 + sub);
            float2 f0 = __half22float2(*reinterpret_cast<__half2*>(&u.x));
            float2 f1 = __half22float2(*reinterpret_cast<__half2*>(&u.y));
            dtp[j] = fmaf(f0.x, sf0.x, fmaf(f0.y, sf0.y,
                      fmaf(f1.x, sf1.x, f1.y * sf1.y)));
        }

#pragma unroll
        for (int i = 0; i < 8; i++) dtp[i] = bmerge(dtp[i], dtp[i + 8], 8, lane);
#pragma unroll
        for (int i = 0; i < 4; i++) dtp[i] = bmerge(dtp[i], dtp[i + 4], 4, lane);
#pragma unroll
        for (int i = 0; i < 2; i++) dtp[i] = bmerge(dtp[i], dtp[i + 2], 2, lane);
        dtp[0] = bmerge(dtp[0], dtp[1], 1, lane);

        float miu = (nidx < v_cates - 1) ? __expf(dtp[0]) : 0.f;
        float miu_self = (vrow < v_cates - 1) ? __expf(ss.y) : 0.f;

        // aggregation: self + 16 neighbors on split even/odd FFMA2 chains
        ulonglong2 cs = __ldg((const ulonglong2*)(cate_emb + (size_t)vrow * D) + sub);
        ull msd = pk2(miu_self, miu_self);
        ull a01a, a23a, a01b, a23b;
        fma2(a01a, msd, cs.x, pk2(0.f, 0.f));
        fma2(a23a, msd, cs.y, pk2(0.f, 0.f));
        a01b = pk2(0.f, 0.f);
        a23b = pk2(0.f, 0.f);
#pragma unroll
        for (int j = 0; j < 16; j += 2) {
            float m0 = __shfl_sync(FULL, miu, base + j);
            int   p0 = __shfl_sync(FULL, nidx, base + j);
            float m1 = __shfl_sync(FULL, miu, base + j + 1);
            int   p1 = __shfl_sync(FULL, nidx, base + j + 1);
            ulonglong2 cv0 = __ldg((const ulonglong2*)(cate_emb + (size_t)p0 * D) + sub);
            ulonglong2 cv1 = __ldg((const ulonglong2*)(cate_emb + (size_t)p1 * D) + sub);
            ull mm0 = pk2(m0, m0);
            ull mm1 = pk2(m1, m1);
            fma2(a01a, mm0, cv0.x, a01a);
            fma2(a23a, mm0, cv0.y, a23a);
            fma2(a01b, mm1, cv1.x, a01b);
            fma2(a23b, mm1, cv1.y, a23b);
        }
        ull acc01, acc23;
        add2(acc01, a01a, a01b);
        add2(acc23, a23a, a23b);
        float2 g01 = upk2(acc01);
        float2 g23 = upk2(acc23);

        // denom reduction (overlaps agg chain — independent of it)
        float dv = miu;
#pragma unroll
        for (int o = 8; o >= 1; o >>= 1)
            dv += __shfl_xor_sync(FULL, dv, o);
        float rden = 1.0f / (dv + miu_self + EPSF);

        // h store (fp16): rs part at e=4sub..4sub+3, agg at e=64+4sub..
        int rt = warp * RPW + 2 * rp + half;
        __half* hrow = sA + rt * ASTRIDE;
        float sc = ss.x;
        __half2 p0h = __floats2half2_rn(sf0.x * sc, sf0.y * sc);
        __half2 p1h = __floats2half2_rn(sf1.x * sc, sf1.y * sc);
        uint2 w0;
        w0.x = *reinterpret_cast<unsigned int*>(&p0h);
        w0.y = *reinterpret_cast<unsigned int*>(&p1h);
        *(uint2*)(hrow + 4 * sub) = w0;

        __half2 q0 = __floats2half2_rn(g01.x * rden, g01.y * rden);
        __half2 q1 = __floats2half2_rn(g23.x * rden, g23.y * rden);
        uint2 w1;
        w1.x = *reinterpret_cast<unsigned int*>(&q0);
        w1.y = *reinterpret_cast<unsigned int*>(&q1);
        *(uint2*)(hrow + 64 + 4 * sub) = w1;
    }
    __syncwarp();

    // ---- Phase 2: HMMA matvec, 16 rows x 64 cols per warp ----
    int gid  = lane >> 2;      // 0..7
    int tid4 = lane & 3;       // 0..3

    float acc[8][4];
#pragma unroll
    for (int n = 0; n < 8; n++)
#pragma unroll
        for (int i = 0; i < 4; i++) acc[n][i] = 0.f;

    const __half* a_base0 = sA + (warp * RPW + gid) * ASTRIDE + tid4 * 2;
    const __half* a_base1 = a_base0 + 8 * ASTRIDE;

#pragma unroll
    for (int k = 0; k < 8; k++) {
        uint32_t a0 = *(const uint32_t*)(a_base0 + k * 16);
        uint32_t a1 = *(const uint32_t*)(a_base1 + k * 16);
        uint32_t a2 = *(const uint32_t*)(a_base0 + k * 16 + 8);
        uint32_t a3 = *(const uint32_t*)(a_base1 + k * 16 + 8);
#pragma unroll
        for (int n = 0; n < 8; n++) {
            uint2 bf = __ldg(&g_Bfrag[(k * 8 + n) * 32 + lane]);
            mma16816(acc[n], a0, a1, a2, a3, bf.x, bf.y);
        }
    }

    // ---- epilogue: bias + ELU + direct stores ----
    int grow0 = rowbase + gid;
    int grow1 = grow0 + 8;
#pragma unroll
    for (int n = 0; n < 8; n++) {
        int col = n * 8 + tid4 * 2;
        float2 bb = *(const float2*)(agg_b + col);
        if (grow0 < n_rows) {
            float v0 = acc[n][0] + bb.x;
            float v1 = acc[n][1] + bb.y;
            v0 = v0 > 0.f ? v0 : expm1f(v0);
            v1 = v1 > 0.f ? v1 : expm1f(v1);
            *(float2*)(out + (size_t)grow0 * D + col) = make_float2(v0, v1);
        }
        if (grow1 < n_rows) {
            float v2 = acc[n][2] + bb.x;
            float v3 = acc[n][3] + bb.y;
            v2 = v2 > 0.f ? v2 : expm1f(v2);
            v3 = v3 > 0.f ? v3 : expm1f(v3);
            *(float2*)(out + (size_t)grow1 * D + col) = make_float2(v2, v3);
        }
    }
}

// ---------------------------------------------------------------------------
// Inputs (metadata order):
//  0 cids, 1 cate_emb_w [Vc,64], 2 scene_emb_w [Vs,64], 3 cate_scene_pad [N,10],
//  4 c_cate_pad [N,16], 5 agg_W [64,128], 6 agg_b [64]   -> out f32 [N,64]
// ---------------------------------------------------------------------------
extern "C" void kernel_launch(void* const* d_in, const int* in_sizes, int n_in,
                              void* d_out, int out_size) {
    const float* cate_emb       = (const float*)d_in[1];
    const float* scene_emb      = (const float*)d_in[2];
    const int*   cate_scene_pad = (const int*)d_in[3];
    const int*   c_cate_pad     = (const int*)d_in[4];
    const float* agg_W          = (const float*)d_in[5];
    const float* agg_b          = (const float*)d_in[6];
    float* out = (float*)d_out;

    int n_rows  = in_sizes[4] / NGH;   // 100000
    int v_cates = in_sizes[1] / D;     // 100000

    int threadsA = 256;
    int blocksA = (n_rows * 16 + threadsA - 1) / threadsA;
    rowsum_kernel<<<blocksA, threadsA>>>(scene_emb, cate_scene_pad, agg_W, n_rows);

    int blocksB = (n_rows + RPB - 1) / RPB;
    main_kernel<<<blocksB, 256>>>(cate_emb, c_cate_pad, agg_b,
                                  out, n_rows, v_cates);
}